// round 7
// baseline (speedup 1.0000x reference)
#include <cuda_runtime.h>
#include <cuda_bf16.h>

// ---------------------------------------------------------------------------
// QuantizedLinear: out = x @ quantize(W)^T + bias
// quantize(w) = clamp(round-half-DOWN(w), -4, 3)  ==  clamp(ceil(w - 0.5), -4, 3)
// W = randn*0.1 -> nonzero quantized entries need |w| >= 5 sigma -> nnz ~ 10.
// Strategy: collect nonzeros (sparse), fill output with bias, apply rank-nnz
// updates. Guarded dense tiled-GEMM fallback if nnz exceeds scratch capacity.
// ---------------------------------------------------------------------------

#define NNZ_CAP (1 << 20)   // 1M entries = 8 MB scratch; fixed seed gives ~10

__device__ int          g_nnz;
__device__ unsigned int g_eidx[NNZ_CAP];  // o*IN + i
__device__ float        g_eval[NNZ_CAP];  // quantized level (nonzero)

__device__ __forceinline__ float quant1(float w) {
    // round-half-down to integer, clamp to [-4, 3]; exact vs jnp argmin ties
    float q = ceilf(w - 0.5f);
    return fmaxf(-4.0f, fminf(3.0f, q));
}

__global__ void k_init() { g_nnz = 0; }

// Fused: quantize+collect W nonzeros AND fill out with bias (grid-stride over
// both regions so HBM read/write overlap in one wave).
__global__ void k_quant_fill(const float* __restrict__ weight,
                             const float* __restrict__ bias,
                             float* __restrict__ out,
                             int IN, int OUT, int B) {
    const long long Wn = (long long)OUT * IN;
    const long long On = (long long)B * OUT;
    const long long W4 = Wn >> 2;
    const long long O4 = On >> 2;
    const long long total = W4 + O4;
    const long long gid = (long long)blockIdx.x * blockDim.x + threadIdx.x;
    const long long stride = (long long)gridDim.x * blockDim.x;

    for (long long t = gid; t < total; t += stride) {
        if (t < W4) {
            float4 w = reinterpret_cast<const float4*>(weight)[t];
            float q0 = quant1(w.x), q1 = quant1(w.y);
            float q2 = quant1(w.z), q3 = quant1(w.w);
            unsigned int base = (unsigned int)(t << 2);
            if (q0 != 0.0f) { int s = atomicAdd(&g_nnz, 1); if (s < NNZ_CAP) { g_eidx[s] = base + 0u; g_eval[s] = q0; } }
            if (q1 != 0.0f) { int s = atomicAdd(&g_nnz, 1); if (s < NNZ_CAP) { g_eidx[s] = base + 1u; g_eval[s] = q1; } }
            if (q2 != 0.0f) { int s = atomicAdd(&g_nnz, 1); if (s < NNZ_CAP) { g_eidx[s] = base + 2u; g_eval[s] = q2; } }
            if (q3 != 0.0f) { int s = atomicAdd(&g_nnz, 1); if (s < NNZ_CAP) { g_eidx[s] = base + 3u; g_eval[s] = q3; } }
        } else {
            long long j = t - W4;                 // float4 index into out
            int col = (int)((j << 2) % OUT);      // OUT % 4 == 0 -> no row wrap
            float4 bv;
            bv.x = __ldg(&bias[col + 0]);
            bv.y = __ldg(&bias[col + 1]);
            bv.z = __ldg(&bias[col + 2]);
            bv.w = __ldg(&bias[col + 3]);
            reinterpret_cast<float4*>(out)[j] = bv;
        }
    }

    // scalar tails (no-op for 4096-divisible shapes, kept for generality)
    long long wtail = Wn & 3, otail = On & 3;
    if (gid < wtail) {
        long long e = (W4 << 2) + gid;
        float q = quant1(weight[e]);
        if (q != 0.0f) { int s = atomicAdd(&g_nnz, 1); if (s < NNZ_CAP) { g_eidx[s] = (unsigned int)e; g_eval[s] = q; } }
    }
    if (gid < otail) {
        long long j = (O4 << 2) + gid;
        out[j] = bias[(int)(j % OUT)];
    }
}

// One thread per batch row; loop over the (tiny) nonzero list.
__global__ void k_sparse_apply(const float* __restrict__ x,
                               float* __restrict__ out,
                               int IN, int OUT, int B) {
    int nnz = g_nnz;
    if (nnz > NNZ_CAP) return;          // dense fallback will handle
    int b = blockIdx.x * blockDim.x + threadIdx.x;
    if (b >= B) return;
    const float* xr = x + (long long)b * IN;
    float*      orw = out + (long long)b * OUT;
    for (int e = 0; e < nnz; e++) {
        unsigned int idx = g_eidx[e];
        float v = g_eval[e];
        int o = (int)(idx / (unsigned int)IN);
        int i = (int)(idx % (unsigned int)IN);
        orw[o] += v * xr[i];
    }
}

// Safety net: dense tiled GEMM, runs ONLY if nnz overflowed the scratch.
// Persistent 64x64 tiles, 256 threads, 4x4 micro-tile per thread.
__global__ void k_dense_fallback(const float* __restrict__ x,
                                 const float* __restrict__ weight,
                                 const float* __restrict__ bias,
                                 float* __restrict__ out,
                                 int IN, int OUT, int B) {
    if (g_nnz <= NNZ_CAP) return;       // cheap early exit (normal path)

    const int TM = 64, TN = 64, TK = 16;
    __shared__ float xs[16][64];
    __shared__ float ws[16][64];

    int tid = threadIdx.x;
    int tx = tid & 15, ty = tid >> 4;
    int tilesM = (B + TM - 1) / TM;
    int tilesN = (OUT + TN - 1) / TN;

    for (int tile = blockIdx.x; tile < tilesM * tilesN; tile += gridDim.x) {
        int tm = tile / tilesN, tn = tile % tilesN;
        int m0 = tm * TM, n0 = tn * TN;
        float acc[4][4];
        #pragma unroll
        for (int i = 0; i < 4; i++)
            #pragma unroll
            for (int j = 0; j < 4; j++) acc[i][j] = 0.0f;

        for (int k0 = 0; k0 < IN; k0 += TK) {
            #pragma unroll
            for (int r = 0; r < 4; r++) {
                int li = tid + r * 256;       // 0..1023
                int k = li >> 6, mm = li & 63;
                int gk = k0 + k;
                int gm = m0 + mm;
                xs[k][mm] = (gm < B && gk < IN)
                          ? x[(long long)gm * IN + gk] : 0.0f;
                int gn = n0 + mm;
                ws[k][mm] = (gn < OUT && gk < IN)
                          ? quant1(weight[(long long)gn * IN + gk]) : 0.0f;
            }
            __syncthreads();
            #pragma unroll
            for (int k = 0; k < TK; k++) {
                float a[4], bb[4];
                #pragma unroll
                for (int i = 0; i < 4; i++) a[i]  = xs[k][ty * 4 + i];
                #pragma unroll
                for (int j = 0; j < 4; j++) bb[j] = ws[k][tx * 4 + j];
                #pragma unroll
                for (int i = 0; i < 4; i++)
                    #pragma unroll
                    for (int j = 0; j < 4; j++) acc[i][j] += a[i] * bb[j];
            }
            __syncthreads();
        }

        #pragma unroll
        for (int i = 0; i < 4; i++) {
            int gm = m0 + ty * 4 + i;
            if (gm >= B) continue;
            #pragma unroll
            for (int j = 0; j < 4; j++) {
                int gn = n0 + tx * 4 + j;
                if (gn < OUT)
                    out[(long long)gm * OUT + gn] = acc[i][j] + __ldg(&bias[gn]);
            }
        }
    }
}

extern "C" void kernel_launch(void* const* d_in, const int* in_sizes, int n_in,
                              void* d_out, int out_size) {
    const float* x      = (const float*)d_in[0];   // [B, IN]
    const float* weight = (const float*)d_in[1];   // [OUT, IN]
    const float* bias   = (const float*)d_in[2];   // [OUT]
    float* out = (float*)d_out;                    // [B, OUT]

    int OUT = in_sizes[2];
    int IN  = in_sizes[1] / OUT;
    int B   = in_sizes[0] / IN;

    k_init<<<1, 1>>>();
    k_quant_fill<<<1184, 256>>>(weight, bias, out, IN, OUT, B);
    k_sparse_apply<<<(B + 255) / 256, 256>>>(x, out, IN, OUT, B);
    k_dense_fallback<<<592, 256>>>(x, weight, bias, out, IN, OUT, B);
}

// round 8
// speedup vs baseline: 1.1570x; 1.1570x over previous
#include <cuda_runtime.h>
#include <cuda_bf16.h>

// ---------------------------------------------------------------------------
// QuantizedLinear: out = x @ quantize(W)^T + bias
// quantize(w) = clamp(ceil(w - 0.5), -4, 3)   (== jnp argmin with first-index ties)
// W = randn*0.1 -> nonzero quantized entries need |w| >= 5 sigma -> nnz ~ 10.
// Plan: 2 kernels.
//   k_quant_fill: blocks [0,WB) quantize W + collect nonzeros (atomic counter);
//                 blocks [WB,grid) fill out with bias (streaming float4 stores).
//   k_apply:      sparse rank-nnz update via fire-and-forget atomicAdd;
//                 guarded dense tiled-GEMM fallback if nnz > cap (never taken);
//                 last-finishing block resets the counter for the next replay.
// ---------------------------------------------------------------------------

#define NNZ_CAP (1 << 20)   // 1M entries = 8 MB scratch

__device__ int          g_nnz;               // zero-initialized; reset by k_apply
__device__ unsigned int g_done;              // ticket for last-block reset
__device__ unsigned int g_eidx[NNZ_CAP];     // o*IN + i
__device__ float        g_eval[NNZ_CAP];     // quantized level (nonzero)

__device__ __forceinline__ float quant1(float w) {
    float q = ceilf(w - 0.5f);               // round-half-down, exact vs argmin
    return fmaxf(-4.0f, fminf(3.0f, q));
}

__global__ void k_quant_fill(const float* __restrict__ weight,
                             const float* __restrict__ bias,
                             float* __restrict__ out,
                             int IN, int OUT, int B, int wblocks) {
    if ((int)blockIdx.x < wblocks) {
        // ---- quantize + collect nonzeros (read 64 MB) ----
        const unsigned Wn = (unsigned)OUT * (unsigned)IN;
        const unsigned W4 = Wn >> 2;
        const unsigned gid = blockIdx.x * blockDim.x + threadIdx.x;
        const unsigned stride = (unsigned)wblocks * blockDim.x;
        const float4* w4p = reinterpret_cast<const float4*>(weight);
        for (unsigned t = gid; t < W4; t += stride) {
            float4 w = __ldcs(&w4p[t]);      // streaming: no reuse
            float q0 = quant1(w.x), q1 = quant1(w.y);
            float q2 = quant1(w.z), q3 = quant1(w.w);
            if ((q0 != 0.f) | (q1 != 0.f) | (q2 != 0.f) | (q3 != 0.f)) {
                unsigned base = t << 2;
                if (q0 != 0.f) { int s = atomicAdd(&g_nnz, 1); if (s < NNZ_CAP) { g_eidx[s] = base + 0u; g_eval[s] = q0; } }
                if (q1 != 0.f) { int s = atomicAdd(&g_nnz, 1); if (s < NNZ_CAP) { g_eidx[s] = base + 1u; g_eval[s] = q1; } }
                if (q2 != 0.f) { int s = atomicAdd(&g_nnz, 1); if (s < NNZ_CAP) { g_eidx[s] = base + 2u; g_eval[s] = q2; } }
                if (q3 != 0.f) { int s = atomicAdd(&g_nnz, 1); if (s < NNZ_CAP) { g_eidx[s] = base + 3u; g_eval[s] = q3; } }
            }
        }
        unsigned tail = Wn & 3u;             // no-op for 4096-divisible shapes
        if (gid < tail) {
            unsigned e = (W4 << 2) + gid;
            float q = quant1(weight[e]);
            if (q != 0.f) { int s = atomicAdd(&g_nnz, 1); if (s < NNZ_CAP) { g_eidx[s] = e; g_eval[s] = q; } }
        }
    } else {
        // ---- fill out with broadcast bias (write 128 MB) ----
        const unsigned gid = (blockIdx.x - wblocks) * blockDim.x + threadIdx.x;
        const unsigned stride = (gridDim.x - wblocks) * blockDim.x;
        if ((OUT & 3) == 0) {
            const unsigned O4 = ((unsigned)B * (unsigned)OUT) >> 2;
            const unsigned OUT4 = (unsigned)OUT >> 2;
            const float4* b4 = reinterpret_cast<const float4*>(bias);
            float4* o4 = reinterpret_cast<float4*>(out);
            if ((OUT4 & (OUT4 - 1)) == 0) {          // power of two: mask
                const unsigned mask = OUT4 - 1;
                for (unsigned t = gid; t < O4; t += stride)
                    __stcs(&o4[t], __ldg(&b4[t & mask]));
            } else {
                for (unsigned t = gid; t < O4; t += stride)
                    __stcs(&o4[t], __ldg(&b4[t % OUT4]));
            }
        } else {                                      // generic scalar path
            const unsigned On = (unsigned)B * (unsigned)OUT;
            for (unsigned t = gid; t < On; t += stride)
                out[t] = __ldg(&bias[t % (unsigned)OUT]);
        }
    }
}

// Sparse apply (normal path) + dense fallback (guarded) + counter reset.
__global__ void k_apply(const float* __restrict__ x,
                        const float* __restrict__ weight,
                        const float* __restrict__ bias,
                        float* __restrict__ out,
                        int IN, int OUT, int B) {
    const int nnz = g_nnz;

    if (nnz <= NNZ_CAP) {
        // Fire-and-forget REDG updates: out[b][o] += v * x[b][i].
        // Parallel over rows per entry; no RMW dependency chain.
        const unsigned nthreads = gridDim.x * blockDim.x;
        const unsigned gid = blockIdx.x * blockDim.x + threadIdx.x;
        for (int e = 0; e < nnz; e++) {
            const unsigned idx = g_eidx[e];
            const float v = g_eval[e];
            const unsigned o = idx / (unsigned)IN;
            const unsigned i = idx % (unsigned)IN;
            for (unsigned b = gid; b < (unsigned)B; b += nthreads)
                atomicAdd(&out[(size_t)b * OUT + o],
                          v * __ldg(&x[(size_t)b * IN + i]));
        }
    } else {
        // Dense tiled-GEMM safety net (only if scratch overflowed; never taken
        // on this dataset — correct but slow by design).
        const int TM = 64, TN = 64, TK = 16;
        __shared__ float xs[16][64];
        __shared__ float ws[16][64];
        int tid = threadIdx.x;
        int tx = tid & 15, ty = tid >> 4;
        int tilesM = (B + TM - 1) / TM;
        int tilesN = (OUT + TN - 1) / TN;
        for (int tile = blockIdx.x; tile < tilesM * tilesN; tile += gridDim.x) {
            int tm = tile / tilesN, tn = tile % tilesN;
            int m0 = tm * TM, n0 = tn * TN;
            float acc[4][4];
            #pragma unroll
            for (int i2 = 0; i2 < 4; i2++)
                #pragma unroll
                for (int j = 0; j < 4; j++) acc[i2][j] = 0.0f;
            for (int k0 = 0; k0 < IN; k0 += TK) {
                #pragma unroll
                for (int r = 0; r < 4; r++) {
                    int li = tid + r * 256;
                    int k = li >> 6, mm = li & 63;
                    int gk = k0 + k, gm = m0 + mm, gn = n0 + mm;
                    xs[k][mm] = (gm < B && gk < IN) ? x[(size_t)gm * IN + gk] : 0.0f;
                    ws[k][mm] = (gn < OUT && gk < IN) ? quant1(weight[(size_t)gn * IN + gk]) : 0.0f;
                }
                __syncthreads();
                #pragma unroll
                for (int k = 0; k < TK; k++) {
                    float a[4], bb[4];
                    #pragma unroll
                    for (int i2 = 0; i2 < 4; i2++) a[i2] = xs[k][ty * 4 + i2];
                    #pragma unroll
                    for (int j = 0; j < 4; j++) bb[j] = ws[k][tx * 4 + j];
                    #pragma unroll
                    for (int i2 = 0; i2 < 4; i2++)
                        #pragma unroll
                        for (int j = 0; j < 4; j++) acc[i2][j] += a[i2] * bb[j];
                }
                __syncthreads();
            }
            #pragma unroll
            for (int i2 = 0; i2 < 4; i2++) {
                int gm = m0 + ty * 4 + i2;
                if (gm >= B) continue;
                #pragma unroll
                for (int j = 0; j < 4; j++) {
                    int gn = n0 + tx * 4 + j;
                    if (gn < OUT)
                        out[(size_t)gm * OUT + gn] = acc[i2][j] + __ldg(&bias[gn]);
                }
            }
        }
    }

    // Last-finishing block resets the counter for the next graph replay.
    // Safe: every block read g_nnz before incrementing the ticket, so the
    // reset happens only after all reads. Kernel-launch boundary orders the
    // reset vs. the next call's atomics.
    __syncthreads();
    if (threadIdx.x == 0) {
        unsigned t = atomicAdd(&g_done, 1u);
        if (t == gridDim.x - 1) { g_done = 0u; g_nnz = 0; }
    }
}

extern "C" void kernel_launch(void* const* d_in, const int* in_sizes, int n_in,
                              void* d_out, int out_size) {
    const float* x      = (const float*)d_in[0];   // [B, IN]
    const float* weight = (const float*)d_in[1];   // [OUT, IN]
    const float* bias   = (const float*)d_in[2];   // [OUT]
    float* out = (float*)d_out;                    // [B, OUT]

    int OUT = in_sizes[2];
    int IN  = in_sizes[1] / OUT;
    int B   = in_sizes[0] / IN;

    // Blocks split proportional to traffic: W read 64 MB : out write 128 MB.
    const int grid = 1184;                // 8 blocks/SM on 148 SMs
    const int wblocks = grid / 3;         // ~395 quantize, ~789 fill

    k_quant_fill<<<grid, 256>>>(weight, bias, out, IN, OUT, B, wblocks);
    k_apply<<<64, 256>>>(x, weight, bias, out, IN, OUT, B);
}